// round 10
// baseline (speedup 1.0000x reference)
#include <cuda_runtime.h>

#define TT 50
#define TR 48
#define SSTART 48
#define SSTOP 49
#define LL 512
#define BB 1024

__device__ int g_order[BB];

__device__ __forceinline__ unsigned long long pack2f(float a, float b) {
    unsigned long long u;
    asm("mov.b64 %0, {%1, %2};" : "=l"(u) : "f"(a), "f"(b));
    return u;
}
__device__ __forceinline__ void unpack2f(unsigned long long u, float& a, float& b) {
    asm("mov.b64 {%0, %1}, %2;" : "=f"(a), "=f"(b) : "l"(u));
}
// d = a*b + d, packed 2xf32 (Blackwell FFMA2)
__device__ __forceinline__ void fma2(unsigned long long& d,
                                     unsigned long long a, unsigned long long b) {
    asm("fma.rn.f32x2 %0, %1, %2, %0;" : "+l"(d) : "l"(a), "l"(b));
}
__device__ __forceinline__ float frcp(float x) {
    float r;
    asm("rcp.approx.f32 %0, %1;" : "=f"(r) : "f"(x));
    return r;
}

// Counting sort of batch indices by DESCENDING length + zero output.
// Sorted adjacency gives near-equal-length pairs for the 2-seq warps.
__global__ void setup_k(const int* __restrict__ lens, float* out) {
    __shared__ int hist[LL + 1];
    const int t = threadIdx.x;
    if (t <= LL) hist[t] = 0;
    if (t == 0) out[0] = 0.0f;
    __syncthreads();
    atomicAdd(&hist[lens[t]], 1);
    __syncthreads();
    if (t == 0) {                       // descending exclusive offsets
        int run = 0;
        for (int l = LL; l >= 1; --l) { int h = hist[l]; hist[l] = run; run += h; }
    }
    __syncthreads();
    int pos = atomicAdd(&hist[lens[t]], 1);
    g_order[pos] = t;
}

// One WARP per PAIR of length-sorted sequences. Lane l (<24) owns states
// 2l, 2l+1 of both sequences. The two recursions share the M registers and
// are interleaved in one loop body so their dependency chains cover each
// other's stalls. No __syncthreads; one __syncwarp per step.
__global__ __launch_bounds__(32) void crf_nll_kernel(
    const float* __restrict__ logits,   // [B, L, T]
    const float* __restrict__ trans,    // [T, T]
    const int*   __restrict__ labels,   // [B, L]
    const int*   __restrict__ lens,     // [B]
    float* __restrict__ out)            // scalar
{
    const int l = threadIdx.x;
    const int sA = (l < 24) ? 2 * l : 0;        // clamped for lanes 24-31
    const int b0 = g_order[2 * blockIdx.x];     // longer (sorted desc)
    const int b1 = g_order[2 * blockIdx.x + 1]; // shorter or equal

    __shared__ __align__(16) float w_s[2][2][TR];   // [buf][seq][state]

    const int len0 = lens[b0];
    const int len1 = lens[b1];
    const float* lr0 = logits + (long)b0 * (LL * TT);
    const float* lr1 = logits + (long)b1 * (LL * TT);
    const int*  lab0 = labels + (long)b0 * LL;
    const int*  lab1 = labels + (long)b1 * LL;

    // M rows (exp of transitions), SHARED by both sequences. START row /
    // STOP column are -1e4 -> exp underflows to exactly 0, matching the
    // reference's logsumexp; both degenerate states drop out.
    unsigned long long MA[24], MB[24];
    const float* trA = trans + sA * TT;
    const float* trB = trA + TT;
    #pragma unroll
    for (int i = 0; i < 24; ++i) {
        MA[i] = pack2f(__expf(trA[2 * i]), __expf(trA[2 * i + 1]));
        MB[i] = pack2f(__expf(trB[2 * i]), __expf(trB[2 * i + 1]));
    }
    const float eStopA = __expf(trans[SSTOP * TT + sA]);
    const float eStopB = __expf(trans[SSTOP * TT + sA + 1]);

    // ---- gold-path scores: half-warp per sequence, strided gathers
    const float* lrS  = (l < 16) ? lr0  : lr1;
    const int*   labS = (l < 16) ? lab0 : lab1;
    const int    lenS = (l < 16) ? len0 : len1;
    const int s16 = l & 15;
    float em = 0.0f, tc = 0.0f;
    for (int t = s16; t < lenS; t += 16) {
        int lb = labS[t];
        em += lrS[t * TT + lb];
        if (t > 0) tc += trans[lb * TT + labS[t - 1]];
    }
    if (s16 == 0)
        tc += trans[labS[0] * TT + SSTART] + trans[SSTOP * TT + labS[lenS - 1]];
    float sc = em + tc;
    #pragma unroll
    for (int d = 8; d >= 1; d >>= 1)            // stays within each half-warp
        sc += __shfl_xor_sync(0xFFFFFFFFu, sc, d);
    const float sc0 = __shfl_sync(0xFFFFFFFFu, sc, 0);
    const float sc1 = __shfl_sync(0xFFFFFFFFu, sc, 16);

    // ---- init t = 0 for both sequences
    float w0A = __expf(lr0[sA]     + trA[SSTART]);
    float w0B = __expf(lr0[sA + 1] + trB[SSTART]);
    float w1A = __expf(lr1[sA]     + trA[SSTART]);
    float w1B = __expf(lr1[sA + 1] + trB[SSTART]);
    if (l < 24) {
        *reinterpret_cast<float2*>(&w_s[0][0][2 * l]) = make_float2(w0A, w0B);
        *reinterpret_cast<float2*>(&w_s[0][1][2 * l]) = make_float2(w1A, w1B);
    }
    float el0A, el0B, el1A, el1B;
    {
        float2 g0 = (1 < len0) ? *reinterpret_cast<const float2*>(lr0 + TT + sA)
                               : make_float2(0.0f, 0.0f);
        float2 g1 = (1 < len1) ? *reinterpret_cast<const float2*>(lr1 + TT + sA)
                               : make_float2(0.0f, 0.0f);
        el0A = __expf(g0.x); el0B = __expf(g0.y);
        el1A = __expf(g1.x); el1B = __expf(g1.y);
    }
    float C0 = 0.0f, C1 = 0.0f;
    __syncwarp();

    // ---- interleaved scaled forward recursions (len0 >= len1 by sort)
    int p = 0;
    for (int t = 1; t < len0; ++t) {
        const int tn0 = (t + 1 < len0) ? (t + 1) : t;
        const int tn1 = (t + 1 < len1) ? (t + 1) : (len1 - 1);   // clamped, valid
        const float2 gN0 = *reinterpret_cast<const float2*>(lr0 + tn0 * TT + sA);
        const float2 gN1 = *reinterpret_cast<const float2*>(lr1 + tn1 * TT + sA);
        const bool act1 = (t < len1);

        const ulonglong2* v0 = reinterpret_cast<const ulonglong2*>(w_s[p][0]);
        const ulonglong2* v1 = reinterpret_cast<const ulonglong2*>(w_s[p][1]);
        ulonglong2 q00 = v0[0], q10 = v1[0];
        float w00, wd0, w10, wd1;
        unpack2f(q00.x, w00, wd0);
        unpack2f(q10.x, w10, wd1);
        const float rn0 = frcp(w00);            // MUFU, overlapped
        const float rn1 = frcp(w10);

        unsigned long long a00 = 0, a01 = 0, c00 = 0, c01 = 0;   // seq0
        unsigned long long a10 = 0, a11 = 0, c10 = 0, c11 = 0;   // seq1
        ulonglong2 q01 = v0[1], q11 = v1[1];
        fma2(a00, MA[0], q00.x); fma2(a01, MA[1], q00.y);
        fma2(a10, MA[0], q10.x); fma2(a11, MA[1], q10.y);
        fma2(c00, MB[0], q00.x); fma2(c01, MB[1], q00.y);
        fma2(c10, MB[0], q10.x); fma2(c11, MB[1], q10.y);
        fma2(a00, MA[2], q01.x); fma2(a01, MA[3], q01.y);
        fma2(a10, MA[2], q11.x); fma2(a11, MA[3], q11.y);
        fma2(c00, MB[2], q01.x); fma2(c01, MB[3], q01.y);
        fma2(c10, MB[2], q11.x); fma2(c11, MB[3], q11.y);
        #pragma unroll
        for (int k = 1; k < 6; ++k) {
            ulonglong2 r00 = v0[2 * k], r01 = v0[2 * k + 1];
            ulonglong2 r10 = v1[2 * k], r11 = v1[2 * k + 1];
            fma2(a00, MA[4 * k + 0], r00.x); fma2(a01, MA[4 * k + 1], r00.y);
            fma2(a10, MA[4 * k + 0], r10.x); fma2(a11, MA[4 * k + 1], r10.y);
            fma2(c00, MB[4 * k + 0], r00.x); fma2(c01, MB[4 * k + 1], r00.y);
            fma2(c10, MB[4 * k + 0], r10.x); fma2(c11, MB[4 * k + 1], r10.y);
            fma2(a00, MA[4 * k + 2], r01.x); fma2(a01, MA[4 * k + 3], r01.y);
            fma2(a10, MA[4 * k + 2], r11.x); fma2(a11, MA[4 * k + 3], r11.y);
            fma2(c00, MB[4 * k + 2], r01.x); fma2(c01, MB[4 * k + 3], r01.y);
            fma2(c10, MB[4 * k + 2], r11.x); fma2(c11, MB[4 * k + 3], r11.y);
        }
        float f0, f1, f2, f3, g0, g1, g2, g3;
        float h0, h1, h2, h3, i0, i1, i2, i3;
        unpack2f(a00, f0, f1); unpack2f(a01, f2, f3);
        unpack2f(c00, g0, g1); unpack2f(c01, g2, g3);
        unpack2f(a10, h0, h1); unpack2f(a11, h2, h3);
        unpack2f(c10, i0, i1); unpack2f(c11, i2, i3);
        const float S0A = (f0 + f1) + (f2 + f3);
        const float S0B = (g0 + g1) + (g2 + g3);
        const float S1A = (h0 + h1) + (h2 + h3);
        const float S1B = (i0 + i1) + (i2 + i3);

        // seq0 commit (always)
        w0A = el0A * S0A * rn0;
        w0B = el0B * S0B * rn0;
        if (l < 24)
            *reinterpret_cast<float2*>(&w_s[p ^ 1][0][2 * l]) = make_float2(w0A, w0B);
        C0  += __logf(w00);
        el0A = __expf(gN0.x);
        el0B = __expf(gN0.y);

        // seq1 commit (predicated; uncommitted garbage is discarded)
        if (act1) {
            w1A = el1A * S1A * rn1;
            w1B = el1B * S1B * rn1;
            if (l < 24)
                *reinterpret_cast<float2*>(&w_s[p ^ 1][1][2 * l]) = make_float2(w1A, w1B);
            C1  += __logf(w10);
            el1A = __expf(gN1.x);
            el1B = __expf(gN1.y);
        }
        __syncwarp();
        p ^= 1;
    }

    // ---- partitions
    float f0 = (l < 24) ? (w0A * eStopA + w0B * eStopB) : 0.0f;
    float f1 = (l < 24) ? (w1A * eStopA + w1B * eStopB) : 0.0f;
    #pragma unroll
    for (int d = 16; d >= 1; d >>= 1) {
        f0 += __shfl_xor_sync(0xFFFFFFFFu, f0, d);
        f1 += __shfl_xor_sync(0xFFFFFFFFu, f1, d);
    }

    if (l == 0) {
        float part0 = C0 + __logf(f0);
        float part1 = C1 + __logf(f1);
        atomicAdd(out, ((part0 - sc0) + (part1 - sc1)) * (1.0f / (float)BB));
    }
}

extern "C" void kernel_launch(void* const* d_in, const int* in_sizes, int n_in,
                              void* d_out, int out_size) {
    const float* logits = (const float*)d_in[0];
    const float* trans  = (const float*)d_in[1];
    const int*   labels = (const int*)d_in[2];
    const int*   lens   = (const int*)d_in[3];
    float* out = (float*)d_out;

    setup_k<<<1, BB>>>(lens, out);
    crf_nll_kernel<<<BB / 2, 32>>>(logits, trans, labels, lens, out);
}